// round 8
// baseline (speedup 1.0000x reference)
#include <cuda_runtime.h>
#include <math.h>

#define NN 50000
#define NE 400000
#define NHID 128
#define INDIM 256
#define NT 4
#define NR 5
#define NH 4
#define DK 32
#define MAXLEN 240
#define NLAYERS 2

// ---------------- scratch (device globals; no allocation) ----------------
__device__ float d_h[(size_t)NN * NHID];
__device__ float d_h2[(size_t)NN * NHID];
__device__ float d_Kn[(size_t)NN * NHID];
__device__ float d_Vn[(size_t)NN * NHID];
__device__ float d_Qn[(size_t)NN * NHID];
__device__ float d_QR[(size_t)NN * NR * NHID];
__device__ float d_denom[(size_t)NN * NH];
__device__ float d_aggr[(size_t)NN * NHID];
__device__ float d_rtetab[MAXLEN * NHID];
__device__ float d_Krte[NT * MAXLEN * NHID];
__device__ float d_Vrte[NT * MAXLEN * NHID];
__device__ int d_perm[NN];
__device__ int d_cnt[NT];
__device__ int d_off[NT + 1];
__device__ int d_cur[NT];
// CSR by dst
__device__ int d_indeg[NN];
__device__ int d_rowptr[NN + 1];
__device__ int d_cur2[NN];
__device__ unsigned d_csr[NE];

__device__ __forceinline__ float gelu_f(float x) {
    return 0.5f * x * (1.0f + erff(x * 0.70710678118654752440f));
}

// ---------------- type bucketing (counting sort by node type) ----------------
__global__ void k_count(const int* __restrict__ nt) {
    int n = blockIdx.x * 256 + threadIdx.x;
    if (n < NN) atomicAdd(&d_cnt[nt[n]], 1);
}
__global__ void k_scan() {
    int s = 0;
    for (int t = 0; t < NT; t++) { d_off[t] = s; d_cur[t] = s; s += d_cnt[t]; }
    d_off[NT] = s;
}
__global__ void k_scatter(const int* __restrict__ nt) {
    int n = blockIdx.x * 256 + threadIdx.x;
    if (n < NN) {
        int p = atomicAdd(&d_cur[nt[n]], 1);
        d_perm[p] = n;
    }
}

// ---------------- CSR build (once; graph is layer-invariant) ----------------
__global__ void k_indeg(const int* __restrict__ ei) {
    int e = blockIdx.x * 256 + threadIdx.x;
    if (e < NE) atomicAdd(&d_indeg[ei[NE + e]], 1);
}
__global__ __launch_bounds__(1024) void k_csr_scan() {
    __shared__ int sh[1024];
    int t = threadIdx.x;
    const int CH = (NN + 1023) / 1024;
    int beg = t * CH; if (beg > NN) beg = NN;
    int end = beg + CH; if (end > NN) end = NN;
    int s = 0;
    for (int i = beg; i < end; i++) s += d_indeg[i];
    sh[t] = s;
    __syncthreads();
    for (int off = 1; off < 1024; off <<= 1) {
        int v = (t >= off) ? sh[t - off] : 0;
        __syncthreads();
        sh[t] += v;
        __syncthreads();
    }
    int pre = (t == 0) ? 0 : sh[t - 1];
    for (int i = beg; i < end; i++) {
        d_rowptr[i] = pre; d_cur2[i] = pre; pre += d_indeg[i];
    }
    if (t == 1023) d_rowptr[NN] = pre;
}
// payload: src (16b) | rel (3b) | kid = type*MAXLEN+time (10b)
__global__ void k_csr_scatter(const int* __restrict__ ei, const int* __restrict__ et,
                              const int* __restrict__ etime, const int* __restrict__ nty) {
    int e = blockIdx.x * 256 + threadIdx.x;
    if (e >= NE) return;
    int src = ei[e], dst = ei[NE + e];
    unsigned kid = (unsigned)(nty[src] * MAXLEN + etime[e]);
    unsigned pk = (unsigned)src | ((unsigned)et[e] << 16) | (kid << 19);
    int pos = atomicAdd(&d_cur2[dst], 1);
    d_csr[pos] = pk;
}

// ---------------- type-selected GEMM: C[n,:] = A[n,:] @ W[type[n]] + b ----------------
// 64x128 tile, 256 threads, 8x4 per thread, BK=32 (74 regs).
// EPI: 0 = bias, 1 = bias+GELU, 2 = bias then v*sig(skip[t]) + Hres*(1-sig)
// NORMA: A rows are d_aggr; apply x -> gelu(x / denom[row,head]) while loading.
template <int K, int EPI, int NORMA>
__global__ __launch_bounds__(256) void typed_gemm(
    const float* __restrict__ A, const float* __restrict__ W,
    const float* __restrict__ Bias, const float* __restrict__ skipv,
    const float* __restrict__ Hres, float* __restrict__ C)
{
    int b = blockIdx.x;
    int t = -1, row0 = 0, mrows = 0;
#pragma unroll
    for (int tt = 0; tt < NT; tt++) {
        if (t < 0) {
            int c = d_cnt[tt];
            int ntile = (c + 63) >> 6;
            if (b < ntile) {
                t = tt;
                row0 = d_off[tt] + b * 64;
                mrows = c - b * 64;
                if (mrows > 64) mrows = 64;
            } else {
                b -= ntile;
            }
        }
    }
    if (t < 0) return;

    __shared__ float As[32][68];
    __shared__ float Bs[32][128];
    __shared__ int rowidx[64];
    __shared__ float rdn[64][4];
    int tid = threadIdx.x;
    if (tid < 64) {
        int m = tid < mrows ? tid : (mrows - 1);
        int gr = d_perm[row0 + m];
        rowidx[tid] = gr;
        if (NORMA) {
            float4 dn = *(const float4*)(d_denom + (size_t)gr * NH);
            rdn[tid][0] = 1.f / (dn.x + 1e-16f);
            rdn[tid][1] = 1.f / (dn.y + 1e-16f);
            rdn[tid][2] = 1.f / (dn.z + 1e-16f);
            rdn[tid][3] = 1.f / (dn.w + 1e-16f);
        }
    }
    __syncthreads();

    const float* Wt = W + (size_t)t * K * NHID;
    float acc[8][4];
#pragma unroll
    for (int j = 0; j < 8; j++)
#pragma unroll
        for (int i = 0; i < 4; i++) acc[j][i] = 0.f;
    int tm = tid >> 5, tn = tid & 31;

    for (int k0 = 0; k0 < K; k0 += 32) {
#pragma unroll
        for (int it = 0; it < 2; it++) {
            int s = tid + it * 256;
            int m = s >> 3, k4 = (s & 7) * 4;
            float4 av = *(const float4*)(A + (size_t)rowidx[m] * K + k0 + k4);
            if (NORMA) {
                float dn = rdn[m][k0 >> 5];
                av.x = gelu_f(av.x * dn); av.y = gelu_f(av.y * dn);
                av.z = gelu_f(av.z * dn); av.w = gelu_f(av.w * dn);
            }
            As[k4 + 0][m] = av.x; As[k4 + 1][m] = av.y;
            As[k4 + 2][m] = av.z; As[k4 + 3][m] = av.w;
        }
#pragma unroll
        for (int it = 0; it < 4; it++) {
            int s = tid + it * 256;
            int kk = s >> 5, c4 = (s & 31) * 4;
            *(float4*)&Bs[kk][c4] = *(const float4*)(Wt + (size_t)(k0 + kk) * NHID + c4);
        }
        __syncthreads();
#pragma unroll
        for (int kk = 0; kk < 32; kk++) {
            float4 a0 = *(const float4*)&As[kk][tm * 8];
            float4 a1 = *(const float4*)&As[kk][tm * 8 + 4];
            float4 bv = *(const float4*)&Bs[kk][tn * 4];
            float av[8] = {a0.x, a0.y, a0.z, a0.w, a1.x, a1.y, a1.z, a1.w};
#pragma unroll
            for (int j = 0; j < 8; j++) {
                acc[j][0] += av[j] * bv.x;
                acc[j][1] += av[j] * bv.y;
                acc[j][2] += av[j] * bv.z;
                acc[j][3] += av[j] * bv.w;
            }
        }
        __syncthreads();
    }

    float4 bias = *(const float4*)(Bias + t * NHID + tn * 4);
    float sg = 0.f, om = 0.f;
    if (EPI == 2) {
        float sv = skipv[t];
        sg = 1.f / (1.f + expf(-sv));
        om = 1.f - sg;
    }
#pragma unroll
    for (int j = 0; j < 8; j++) {
        int m = tm * 8 + j;
        if (m < mrows) {
            int gr = rowidx[m];
            float4 v;
            v.x = acc[j][0] + bias.x; v.y = acc[j][1] + bias.y;
            v.z = acc[j][2] + bias.z; v.w = acc[j][3] + bias.w;
            if (EPI == 1) {
                v.x = gelu_f(v.x); v.y = gelu_f(v.y);
                v.z = gelu_f(v.z); v.w = gelu_f(v.w);
            }
            if (EPI == 2) {
                float4 hv = *(const float4*)(Hres + (size_t)gr * NHID + tn * 4);
                v.x = v.x * sg + hv.x * om; v.y = v.y * sg + hv.y * om;
                v.z = v.z * sg + hv.z * om; v.w = v.w * sg + hv.w * om;
            }
            *(float4*)(C + (size_t)gr * NHID + tn * 4) = v;
        }
    }
}

// ---------------- QR: Out[n,r,h*32+d] = s * sum_k RA[r,h,d,k] * Q[n,h*32+k] --
__global__ __launch_bounds__(640) void qr_kernel(
    const float* __restrict__ In, const float* __restrict__ M,
    const float* __restrict__ pri, float scale, float* __restrict__ Out)
{
    int tid = threadIdx.x;
    int r = tid >> 7, rem = tid & 127, h = rem >> 5, d = rem & 31;
    float s = scale * pri[r * NH + h];
    float ra[DK];
    const float* base = M + (((size_t)(r * NH + h) * DK + d) * DK);
#pragma unroll
    for (int k = 0; k < DK; k++) ra[k] = base[k] * s;
    __shared__ float qs[64][NHID];
    int n0 = blockIdx.x * 64;
    for (int i = tid; i < 64 * NHID; i += 640) {
        int ni = i >> 7, c = i & 127;
        int n = n0 + ni;
        qs[ni][c] = (n < NN) ? In[(size_t)n * NHID + c] : 0.f;
    }
    __syncthreads();
    int nmax = NN - n0;
    if (nmax > 64) nmax = 64;
    for (int ni = 0; ni < nmax; ni++) {
        float acc = 0.f;
#pragma unroll
        for (int k4 = 0; k4 < 8; k4++) {
            float4 q4 = *(const float4*)&qs[ni][h * DK + k4 * 4];
            acc += ra[k4 * 4] * q4.x + ra[k4 * 4 + 1] * q4.y +
                   ra[k4 * 4 + 2] * q4.z + ra[k4 * 4 + 3] * q4.w;
        }
        Out[((size_t)(n0 + ni) * NR + r) * NHID + h * DK + d] = acc;
    }
}

// ---------------- RTE tables ----------------
__global__ void k_rtetab(const float* __restrict__ emb, const float* __restrict__ W,
                         const float* __restrict__ bvec) {
    __shared__ float xs[NHID];
    int tmv = blockIdx.x, c = threadIdx.x;
    xs[c] = emb[tmv * NHID + c];
    __syncthreads();
    float acc = bvec[c];
#pragma unroll 8
    for (int k = 0; k < NHID; k++) acc += xs[k] * W[k * NHID + c];
    d_rtetab[tmv * NHID + c] = acc;
}

__global__ void k_rteproj(const float* __restrict__ W, float* __restrict__ Out) {
    __shared__ float xs[NHID];
    int tmv = blockIdx.x, t = blockIdx.y, c = threadIdx.x;
    xs[c] = d_rtetab[tmv * NHID + c];
    __syncthreads();
    const float* Wt = W + (size_t)t * NHID * NHID;
    float acc = 0.f;
#pragma unroll 8
    for (int k = 0; k < NHID; k++) acc += xs[k] * Wt[k * NHID + c];
    Out[((size_t)t * MAXLEN + tmv) * NHID + c] = acc;
}

// ---------------- CSR edge kernel: warp per dst node ----------------
// Per dst: walk incoming edges; w_e = exp(QR[dst,r]·(Kn[src]+Krte));
// accumulate denom and per-relation S_r = sum w_e*(Vn[src]+Vrte);
// epilogue: aggr = sum_r RM_r S_r (RM in smem), denom written for NORMA gemm.
#define EW_WARPS 16
#define S_STRIDE 36           // padded per-head stride (bank-conflict-free)
#define SMEM_RM_FLOATS (NR * NH * DK * DK)            // 20480
#define SMEM_S_FLOATS (EW_WARPS * NR * NH * S_STRIDE) // 11520
__global__ __launch_bounds__(512) void k_edge_csr(const float* __restrict__ RM) {
    extern __shared__ float smem[];
    float* sRM = smem;
    int tid = threadIdx.x;
    for (int i = tid; i < SMEM_RM_FLOATS; i += 512) sRM[i] = RM[i];
    __syncthreads();

    int w = tid >> 5, lane = tid & 31;
    int dst = blockIdx.x * EW_WARPS + w;
    if (dst >= NN) return;
    int h = lane >> 3;
    int d0 = (lane & 7) * 4;
    int beg = d_rowptr[dst], end = d_rowptr[dst + 1];

    const float4* Kn4 = (const float4*)d_Kn;
    const float4* Vn4 = (const float4*)d_Vn;
    const float4* Kr4 = (const float4*)d_Krte;
    const float4* Vr4 = (const float4*)d_Vrte;
    const float4* Q4 = (const float4*)d_QR;
    float4* Ag4 = (float4*)d_aggr;

    if (beg == end) {
        if ((lane & 7) == 0) d_denom[(size_t)dst * NH + h] = 0.f;
        float4 z; z.x = z.y = z.z = z.w = 0.f;
        Ag4[(size_t)dst * 32 + lane] = z;
        return;
    }

    float4 qr0 = Q4[((size_t)dst * NR + 0) * 32 + lane];
    float4 qr1 = Q4[((size_t)dst * NR + 1) * 32 + lane];
    float4 qr2 = Q4[((size_t)dst * NR + 2) * 32 + lane];
    float4 qr3 = Q4[((size_t)dst * NR + 3) * 32 + lane];
    float4 qr4 = Q4[((size_t)dst * NR + 4) * 32 + lane];

    float4 S0, S1, S2, S3, S4;
    S0.x = S0.y = S0.z = S0.w = 0.f; S1 = S0; S2 = S0; S3 = S0; S4 = S0;
    float den = 0.f;

    for (int e = beg; e < end; e++) {
        unsigned pk = d_csr[e];
        int src = pk & 0xffff;
        int r = (pk >> 16) & 7;
        int kid = pk >> 19;
        float4 kv = Kn4[(size_t)src * 32 + lane];
        float4 kr = Kr4[(size_t)kid * 32 + lane];
        float4 q4 = (r == 0) ? qr0 : (r == 1) ? qr1 : (r == 2) ? qr2
                  : (r == 3) ? qr3 : qr4;
        float p = (kv.x + kr.x) * q4.x + (kv.y + kr.y) * q4.y +
                  (kv.z + kr.z) * q4.z + (kv.w + kr.w) * q4.w;
        p += __shfl_xor_sync(0xffffffffu, p, 1);
        p += __shfl_xor_sync(0xffffffffu, p, 2);
        p += __shfl_xor_sync(0xffffffffu, p, 4);
        float wgt = expf(p);
        den += wgt;
        float4 vv = Vn4[(size_t)src * 32 + lane];
        float4 vr = Vr4[(size_t)kid * 32 + lane];
        float4 m4;
        m4.x = wgt * (vv.x + vr.x); m4.y = wgt * (vv.y + vr.y);
        m4.z = wgt * (vv.z + vr.z); m4.w = wgt * (vv.w + vr.w);
        if (r == 0)      { S0.x += m4.x; S0.y += m4.y; S0.z += m4.z; S0.w += m4.w; }
        else if (r == 1) { S1.x += m4.x; S1.y += m4.y; S1.z += m4.z; S1.w += m4.w; }
        else if (r == 2) { S2.x += m4.x; S2.y += m4.y; S2.z += m4.z; S2.w += m4.w; }
        else if (r == 3) { S3.x += m4.x; S3.y += m4.y; S3.z += m4.z; S3.w += m4.w; }
        else             { S4.x += m4.x; S4.y += m4.y; S4.z += m4.z; S4.w += m4.w; }
    }

    if ((lane & 7) == 0) d_denom[(size_t)dst * NH + h] = den;

    // stage S into padded smem: [warp][r][h*S_STRIDE + i]
    float* sp = smem + SMEM_RM_FLOATS + w * (NR * NH * S_STRIDE);
    *(float4*)&sp[0 * NH * S_STRIDE + h * S_STRIDE + d0] = S0;
    *(float4*)&sp[1 * NH * S_STRIDE + h * S_STRIDE + d0] = S1;
    *(float4*)&sp[2 * NH * S_STRIDE + h * S_STRIDE + d0] = S2;
    *(float4*)&sp[3 * NH * S_STRIDE + h * S_STRIDE + d0] = S3;
    *(float4*)&sp[4 * NH * S_STRIDE + h * S_STRIDE + d0] = S4;
    __syncwarp();

    // aggr[h, d] = sum_r sum_i S_r[h,i] * RM[r,h,i,d]
    float4 o; o.x = o.y = o.z = o.w = 0.f;
#pragma unroll
    for (int r = 0; r < NR; r++) {
        const float* rmb = &sRM[((size_t)(r * NH + h) * DK) * DK + d0];
        const float* sb = &sp[r * NH * S_STRIDE + h * S_STRIDE];
#pragma unroll 8
        for (int i = 0; i < DK; i++) {
            float s = sb[i];
            float4 m = *(const float4*)&rmb[(size_t)i * DK];
            o.x += s * m.x; o.y += s * m.y; o.z += s * m.z; o.w += s * m.w;
        }
    }
    Ag4[(size_t)dst * 32 + lane] = o;
}

// ---------------- launch ----------------
extern "C" void kernel_launch(void* const* d_in, const int* in_sizes, int n_in,
                              void* d_out, int out_size) {
    (void)in_sizes; (void)n_in; (void)out_size;
    const float* node_feature = (const float*)d_in[0];
    const float* adapt_W = (const float*)d_in[1];
    const float* adapt_b = (const float*)d_in[2];
    const float* Wk = (const float*)d_in[3];
    const float* bk = (const float*)d_in[4];
    const float* Wq = (const float*)d_in[5];
    const float* bq = (const float*)d_in[6];
    const float* Wv = (const float*)d_in[7];
    const float* bv = (const float*)d_in[8];
    const float* Wa = (const float*)d_in[9];
    const float* ba = (const float*)d_in[10];
    const float* rel_pri = (const float*)d_in[11];
    const float* rel_att = (const float*)d_in[12];
    const float* rel_msg = (const float*)d_in[13];
    const float* skip = (const float*)d_in[14];
    const float* rte_emb = (const float*)d_in[15];
    const float* rte_W = (const float*)d_in[16];
    const float* rte_b = (const float*)d_in[17];
    const int* node_type = (const int*)d_in[18];
    const int* edge_index = (const int*)d_in[19];
    const int* edge_type = (const int*)d_in[20];
    const int* edge_time = (const int*)d_in[21];
    float* out = (float*)d_out;

    void* p;
    float *p_h, *p_h2, *p_Kn, *p_Vn, *p_Qn, *p_QR, *p_aggr, *p_Krte, *p_Vrte;
    int *p_cnt, *p_indeg;
    cudaGetSymbolAddress(&p, d_h);     p_h = (float*)p;
    cudaGetSymbolAddress(&p, d_h2);    p_h2 = (float*)p;
    cudaGetSymbolAddress(&p, d_Kn);    p_Kn = (float*)p;
    cudaGetSymbolAddress(&p, d_Vn);    p_Vn = (float*)p;
    cudaGetSymbolAddress(&p, d_Qn);    p_Qn = (float*)p;
    cudaGetSymbolAddress(&p, d_QR);    p_QR = (float*)p;
    cudaGetSymbolAddress(&p, d_aggr);  p_aggr = (float*)p;
    cudaGetSymbolAddress(&p, d_Krte);  p_Krte = (float*)p;
    cudaGetSymbolAddress(&p, d_Vrte);  p_Vrte = (float*)p;
    cudaGetSymbolAddress(&p, d_cnt);   p_cnt = (int*)p;
    cudaGetSymbolAddress(&p, d_indeg); p_indeg = (int*)p;

    const int NBN = (NN + 255) / 256;
    const int NBE = (NE + 255) / 256;
    const int GT = NN / 64 + NT + 2;   // upper bound on typed-gemm tiles
    const float inv_sqrt_dk = 0.17677669529663687f; // 1/sqrt(32)
    const int EW_SMEM = (SMEM_RM_FLOATS + SMEM_S_FLOATS) * (int)sizeof(float);
    cudaFuncSetAttribute(k_edge_csr, cudaFuncAttributeMaxDynamicSharedMemorySize,
                         EW_SMEM);

    // type bucketing
    cudaMemsetAsync(p_cnt, 0, NT * sizeof(int));
    k_count<<<NBN, 256>>>(node_type);
    k_scan<<<1, 1>>>();
    k_scatter<<<NBN, 256>>>(node_type);

    // CSR by dst (once)
    cudaMemsetAsync(p_indeg, 0, NN * sizeof(int));
    k_indeg<<<NBE, 256>>>(edge_index);
    k_csr_scan<<<1, 1024>>>();
    k_csr_scatter<<<NBE, 256>>>(edge_index, edge_type, edge_time, node_type);

    // input adaptation: h = gelu(x @ adapt_W[t] + adapt_b[t])
    typed_gemm<INDIM, 1, 0><<<GT, 256>>>(node_feature, adapt_W, adapt_b,
                                         nullptr, nullptr, p_h);

    const float* hin = p_h;
    for (int l = 0; l < NLAYERS; l++) {
        const float* Wk_l = Wk + (size_t)l * NT * NHID * NHID;
        const float* Wq_l = Wq + (size_t)l * NT * NHID * NHID;
        const float* Wv_l = Wv + (size_t)l * NT * NHID * NHID;
        const float* Wa_l = Wa + (size_t)l * NT * NHID * NHID;
        const float* bk_l = bk + (size_t)l * NT * NHID;
        const float* bq_l = bq + (size_t)l * NT * NHID;
        const float* bv_l = bv + (size_t)l * NT * NHID;
        const float* ba_l = ba + (size_t)l * NT * NHID;
        const float* ra_l = rel_att + (size_t)l * NR * NH * DK * DK;
        const float* rm_l = rel_msg + (size_t)l * NR * NH * DK * DK;
        const float* pri_l = rel_pri + (size_t)l * NR * NH;
        const float* skip_l = skip + (size_t)l * NT;
        float* hout = (l == NLAYERS - 1) ? out : p_h2;

        // per-node K/Q/V
        typed_gemm<NHID, 0, 0><<<GT, 256>>>(hin, Wk_l, bk_l, nullptr, nullptr, p_Kn);
        typed_gemm<NHID, 0, 0><<<GT, 256>>>(hin, Wq_l, bq_l, nullptr, nullptr, p_Qn);
        typed_gemm<NHID, 0, 0><<<GT, 256>>>(hin, Wv_l, bv_l, nullptr, nullptr, p_Vn);

        // RTE tables
        k_rtetab<<<MAXLEN, NHID>>>(rte_emb, rte_W + (size_t)l * NHID * NHID,
                                   rte_b + (size_t)l * NHID);
        {
            dim3 g(MAXLEN, NT);
            k_rteproj<<<g, NHID>>>(Wk_l, p_Krte);
            k_rteproj<<<g, NHID>>>(Wv_l, p_Vrte);
        }

        // relation-transformed Q per node (pri/sqrt(dk) folded in)
        qr_kernel<<<(NN + 63) / 64, 640>>>(p_Qn, ra_l, pri_l, inv_sqrt_dk, p_QR);

        // CSR edge pass (no atomics, no memsets)
        k_edge_csr<<<(NN + EW_WARPS - 1) / EW_WARPS, 512, EW_SMEM>>>(rm_l);

        // output transform + gated skip, with normalize+GELU fused into A-load
        typed_gemm<NHID, 2, 1><<<GT, 256>>>(p_aggr, Wa_l, ba_l, skip_l, hin, hout);
        hin = hout;
        if (l == 0) { float* tmp = p_h; p_h = p_h2; p_h2 = tmp; }
    }
}

// round 11
// speedup vs baseline: 1.1181x; 1.1181x over previous
#include <cuda_runtime.h>
#include <math.h>

#define NN 50000
#define NE 400000
#define NHID 128
#define INDIM 256
#define NT 4
#define NR 5
#define NH 4
#define DK 32
#define MAXLEN 240
#define NLAYERS 2

// ---------------- scratch (device globals; no allocation) ----------------
__device__ float d_h[(size_t)NN * NHID];
__device__ float d_h2[(size_t)NN * NHID];
__device__ float d_Kn[(size_t)NN * NHID];
__device__ float d_Vn[(size_t)NN * NHID];
__device__ float d_Qn[(size_t)NN * NHID];
__device__ float d_QR[(size_t)NN * NR * NHID];
__device__ float d_S[(size_t)NN * NR * NHID];
__device__ float d_denom[(size_t)NN * NH];
__device__ float d_aggr[(size_t)NN * NHID];
__device__ float d_rtetab[MAXLEN * NHID];
__device__ float d_Krte[NT * MAXLEN * NHID];
__device__ float d_Vrte[NT * MAXLEN * NHID];
__device__ int d_perm[NN];
__device__ int d_cnt[NT];
__device__ int d_off[NT + 1];
__device__ int d_cur[NT];
// CSR by dst
__device__ int d_indeg[NN];
__device__ int d_rowptr[NN + 1];
__device__ int d_cur2[NN];
__device__ unsigned d_csr[NE];

__device__ __forceinline__ float gelu_f(float x) {
    return 0.5f * x * (1.0f + erff(x * 0.70710678118654752440f));
}

// ---------------- type bucketing (counting sort by node type) ----------------
__global__ void k_count(const int* __restrict__ nt) {
    int n = blockIdx.x * 256 + threadIdx.x;
    if (n < NN) atomicAdd(&d_cnt[nt[n]], 1);
}
__global__ void k_scan() {
    int s = 0;
    for (int t = 0; t < NT; t++) { d_off[t] = s; d_cur[t] = s; s += d_cnt[t]; }
    d_off[NT] = s;
}
__global__ void k_scatter(const int* __restrict__ nt) {
    int n = blockIdx.x * 256 + threadIdx.x;
    if (n < NN) {
        int p = atomicAdd(&d_cur[nt[n]], 1);
        d_perm[p] = n;
    }
}

// ---------------- CSR build (once; graph is layer-invariant) ----------------
__global__ void k_indeg(const int* __restrict__ ei) {
    int e = blockIdx.x * 256 + threadIdx.x;
    if (e < NE) atomicAdd(&d_indeg[ei[NE + e]], 1);
}
__global__ __launch_bounds__(1024) void k_csr_scan() {
    __shared__ int sh[1024];
    int t = threadIdx.x;
    const int CH = (NN + 1023) / 1024;
    int beg = t * CH; if (beg > NN) beg = NN;
    int end = beg + CH; if (end > NN) end = NN;
    int s = 0;
    for (int i = beg; i < end; i++) s += d_indeg[i];
    sh[t] = s;
    __syncthreads();
    for (int off = 1; off < 1024; off <<= 1) {
        int v = (t >= off) ? sh[t - off] : 0;
        __syncthreads();
        sh[t] += v;
        __syncthreads();
    }
    int pre = (t == 0) ? 0 : sh[t - 1];
    for (int i = beg; i < end; i++) {
        d_rowptr[i] = pre; d_cur2[i] = pre; pre += d_indeg[i];
    }
    if (t == 1023) d_rowptr[NN] = pre;
}
// payload: src (16b) | rel (3b) | kid = type*MAXLEN+time (10b)
__global__ void k_csr_scatter(const int* __restrict__ ei, const int* __restrict__ et,
                              const int* __restrict__ etime, const int* __restrict__ nty) {
    int e = blockIdx.x * 256 + threadIdx.x;
    if (e >= NE) return;
    int src = ei[e], dst = ei[NE + e];
    unsigned kid = (unsigned)(nty[src] * MAXLEN + etime[e]);
    unsigned pk = (unsigned)src | ((unsigned)et[e] << 16) | (kid << 19);
    int pos = atomicAdd(&d_cur2[dst], 1);
    d_csr[pos] = pk;
}

// ---------------- type-selected GEMM: C[n,:] = A[n,:] @ W[type[n]] + b ----------------
// 64x128 tile, 256 threads, 8x4 per thread, BK=32 (74 regs).
// EPI: 0 = bias, 1 = bias+GELU, 2 = bias then v*sig(skip[t]) + Hres*(1-sig)
// NORMA: A rows are d_aggr; apply x -> gelu(x / denom[row,head]) while loading.
template <int K, int EPI, int NORMA>
__global__ __launch_bounds__(256) void typed_gemm(
    const float* __restrict__ A, const float* __restrict__ W,
    const float* __restrict__ Bias, const float* __restrict__ skipv,
    const float* __restrict__ Hres, float* __restrict__ C)
{
    int b = blockIdx.x;
    int t = -1, row0 = 0, mrows = 0;
#pragma unroll
    for (int tt = 0; tt < NT; tt++) {
        if (t < 0) {
            int c = d_cnt[tt];
            int ntile = (c + 63) >> 6;
            if (b < ntile) {
                t = tt;
                row0 = d_off[tt] + b * 64;
                mrows = c - b * 64;
                if (mrows > 64) mrows = 64;
            } else {
                b -= ntile;
            }
        }
    }
    if (t < 0) return;

    __shared__ float As[32][68];
    __shared__ float Bs[32][128];
    __shared__ int rowidx[64];
    __shared__ float rdn[64][4];
    int tid = threadIdx.x;
    if (tid < 64) {
        int m = tid < mrows ? tid : (mrows - 1);
        int gr = d_perm[row0 + m];
        rowidx[tid] = gr;
        if (NORMA) {
            float4 dn = *(const float4*)(d_denom + (size_t)gr * NH);
            rdn[tid][0] = 1.f / (dn.x + 1e-16f);
            rdn[tid][1] = 1.f / (dn.y + 1e-16f);
            rdn[tid][2] = 1.f / (dn.z + 1e-16f);
            rdn[tid][3] = 1.f / (dn.w + 1e-16f);
        }
    }
    __syncthreads();

    const float* Wt = W + (size_t)t * K * NHID;
    float acc[8][4];
#pragma unroll
    for (int j = 0; j < 8; j++)
#pragma unroll
        for (int i = 0; i < 4; i++) acc[j][i] = 0.f;
    int tm = tid >> 5, tn = tid & 31;

    for (int k0 = 0; k0 < K; k0 += 32) {
#pragma unroll
        for (int it = 0; it < 2; it++) {
            int s = tid + it * 256;
            int m = s >> 3, k4 = (s & 7) * 4;
            float4 av = *(const float4*)(A + (size_t)rowidx[m] * K + k0 + k4);
            if (NORMA) {
                float dn = rdn[m][k0 >> 5];
                av.x = gelu_f(av.x * dn); av.y = gelu_f(av.y * dn);
                av.z = gelu_f(av.z * dn); av.w = gelu_f(av.w * dn);
            }
            As[k4 + 0][m] = av.x; As[k4 + 1][m] = av.y;
            As[k4 + 2][m] = av.z; As[k4 + 3][m] = av.w;
        }
#pragma unroll
        for (int it = 0; it < 4; it++) {
            int s = tid + it * 256;
            int kk = s >> 5, c4 = (s & 31) * 4;
            *(float4*)&Bs[kk][c4] = *(const float4*)(Wt + (size_t)(k0 + kk) * NHID + c4);
        }
        __syncthreads();
#pragma unroll
        for (int kk = 0; kk < 32; kk++) {
            float4 a0 = *(const float4*)&As[kk][tm * 8];
            float4 a1 = *(const float4*)&As[kk][tm * 8 + 4];
            float4 bv = *(const float4*)&Bs[kk][tn * 4];
            float av[8] = {a0.x, a0.y, a0.z, a0.w, a1.x, a1.y, a1.z, a1.w};
#pragma unroll
            for (int j = 0; j < 8; j++) {
                acc[j][0] += av[j] * bv.x;
                acc[j][1] += av[j] * bv.y;
                acc[j][2] += av[j] * bv.z;
                acc[j][3] += av[j] * bv.w;
            }
        }
        __syncthreads();
    }

    float4 bias = *(const float4*)(Bias + t * NHID + tn * 4);
    float sg = 0.f, om = 0.f;
    if (EPI == 2) {
        float sv = skipv[t];
        sg = 1.f / (1.f + expf(-sv));
        om = 1.f - sg;
    }
#pragma unroll
    for (int j = 0; j < 8; j++) {
        int m = tm * 8 + j;
        if (m < mrows) {
            int gr = rowidx[m];
            float4 v;
            v.x = acc[j][0] + bias.x; v.y = acc[j][1] + bias.y;
            v.z = acc[j][2] + bias.z; v.w = acc[j][3] + bias.w;
            if (EPI == 1) {
                v.x = gelu_f(v.x); v.y = gelu_f(v.y);
                v.z = gelu_f(v.z); v.w = gelu_f(v.w);
            }
            if (EPI == 2) {
                float4 hv = *(const float4*)(Hres + (size_t)gr * NHID + tn * 4);
                v.x = v.x * sg + hv.x * om; v.y = v.y * sg + hv.y * om;
                v.z = v.z * sg + hv.z * om; v.w = v.w * sg + hv.w * om;
            }
            *(float4*)(C + (size_t)gr * NHID + tn * 4) = v;
        }
    }
}

// ---------------- QR: Out[n,r,h*32+d] = s * sum_k RA[r,h,d,k] * Q[n,h*32+k] --
__global__ __launch_bounds__(640) void qr_kernel(
    const float* __restrict__ In, const float* __restrict__ M,
    const float* __restrict__ pri, float scale, float* __restrict__ Out)
{
    int tid = threadIdx.x;
    int r = tid >> 7, rem = tid & 127, h = rem >> 5, d = rem & 31;
    float s = scale * pri[r * NH + h];
    float ra[DK];
    const float* base = M + (((size_t)(r * NH + h) * DK + d) * DK);
#pragma unroll
    for (int k = 0; k < DK; k++) ra[k] = base[k] * s;
    __shared__ float qs[64][NHID];
    int n0 = blockIdx.x * 64;
    for (int i = tid; i < 64 * NHID; i += 640) {
        int ni = i >> 7, c = i & 127;
        int n = n0 + ni;
        qs[ni][c] = (n < NN) ? In[(size_t)n * NHID + c] : 0.f;
    }
    __syncthreads();
    int nmax = NN - n0;
    if (nmax > 64) nmax = 64;
    for (int ni = 0; ni < nmax; ni++) {
        float acc = 0.f;
#pragma unroll
        for (int k4 = 0; k4 < 8; k4++) {
            float4 q4 = *(const float4*)&qs[ni][h * DK + k4 * 4];
            acc += ra[k4 * 4] * q4.x + ra[k4 * 4 + 1] * q4.y +
                   ra[k4 * 4 + 2] * q4.z + ra[k4 * 4 + 3] * q4.w;
        }
        Out[((size_t)(n0 + ni) * NR + r) * NHID + h * DK + d] = acc;
    }
}

// ---------------- RTE tables ----------------
__global__ void k_rtetab(const float* __restrict__ emb, const float* __restrict__ W,
                         const float* __restrict__ bvec) {
    __shared__ float xs[NHID];
    int tmv = blockIdx.x, c = threadIdx.x;
    xs[c] = emb[tmv * NHID + c];
    __syncthreads();
    float acc = bvec[c];
#pragma unroll 8
    for (int k = 0; k < NHID; k++) acc += xs[k] * W[k * NHID + c];
    d_rtetab[tmv * NHID + c] = acc;
}

__global__ void k_rteproj(const float* __restrict__ W, float* __restrict__ Out) {
    __shared__ float xs[NHID];
    int tmv = blockIdx.x, t = blockIdx.y, c = threadIdx.x;
    xs[c] = d_rtetab[tmv * NHID + c];
    __syncthreads();
    const float* Wt = W + (size_t)t * NHID * NHID;
    float acc = 0.f;
#pragma unroll 8
    for (int k = 0; k < NHID; k++) acc += xs[k] * Wt[k * NHID + c];
    Out[((size_t)t * MAXLEN + tmv) * NHID + c] = acc;
}

// ---------------- CSR gather: warp per dst; no smem, no RM ----------------
// Per dst: w_e = exp(QR[dst,r]·(Kn[src]+Krte)); denom += w_e;
// S_r += w_e*(Vn[src]+Vrte). Writes S[dst,5,128] contiguously + denom.
__global__ __launch_bounds__(512) void k_edge_gather() {
    int gw = (blockIdx.x * 512 + threadIdx.x) >> 5;
    if (gw >= NN) return;
    int dst = gw;
    int lane = threadIdx.x & 31;
    int h = lane >> 3;
    int beg = d_rowptr[dst], end = d_rowptr[dst + 1];

    const float4* Kn4 = (const float4*)d_Kn;
    const float4* Vn4 = (const float4*)d_Vn;
    const float4* Kr4 = (const float4*)d_Krte;
    const float4* Vr4 = (const float4*)d_Vrte;
    const float4* Q4 = (const float4*)d_QR;
    float4* S4 = (float4*)d_S;

    float4 qr0 = Q4[((size_t)dst * NR + 0) * 32 + lane];
    float4 qr1 = Q4[((size_t)dst * NR + 1) * 32 + lane];
    float4 qr2 = Q4[((size_t)dst * NR + 2) * 32 + lane];
    float4 qr3 = Q4[((size_t)dst * NR + 3) * 32 + lane];
    float4 qr4 = Q4[((size_t)dst * NR + 4) * 32 + lane];

    float4 S0, S1, S2, S3, S4r;
    S0.x = S0.y = S0.z = S0.w = 0.f; S1 = S0; S2 = S0; S3 = S0; S4r = S0;
    float den = 0.f;

    for (int e = beg; e < end; e++) {
        unsigned pk = d_csr[e];
        int src = pk & 0xffff;
        int r = (pk >> 16) & 7;
        int kid = pk >> 19;
        float4 kv = Kn4[(size_t)src * 32 + lane];
        float4 kr = Kr4[(size_t)kid * 32 + lane];
        float4 q4 = (r == 0) ? qr0 : (r == 1) ? qr1 : (r == 2) ? qr2
                  : (r == 3) ? qr3 : qr4;
        float p = (kv.x + kr.x) * q4.x + (kv.y + kr.y) * q4.y +
                  (kv.z + kr.z) * q4.z + (kv.w + kr.w) * q4.w;
        p += __shfl_xor_sync(0xffffffffu, p, 1);
        p += __shfl_xor_sync(0xffffffffu, p, 2);
        p += __shfl_xor_sync(0xffffffffu, p, 4);
        float wgt = expf(p);
        den += wgt;
        float4 vv = Vn4[(size_t)src * 32 + lane];
        float4 vr = Vr4[(size_t)kid * 32 + lane];
        float4 m4;
        m4.x = wgt * (vv.x + vr.x); m4.y = wgt * (vv.y + vr.y);
        m4.z = wgt * (vv.z + vr.z); m4.w = wgt * (vv.w + vr.w);
        if (r == 0)      { S0.x += m4.x; S0.y += m4.y; S0.z += m4.z; S0.w += m4.w; }
        else if (r == 1) { S1.x += m4.x; S1.y += m4.y; S1.z += m4.z; S1.w += m4.w; }
        else if (r == 2) { S2.x += m4.x; S2.y += m4.y; S2.z += m4.z; S2.w += m4.w; }
        else if (r == 3) { S3.x += m4.x; S3.y += m4.y; S3.z += m4.z; S3.w += m4.w; }
        else             { S4r.x += m4.x; S4r.y += m4.y; S4r.z += m4.z; S4r.w += m4.w; }
    }

    if ((lane & 7) == 0) d_denom[(size_t)dst * NH + h] = den;
    S4[((size_t)dst * NR + 0) * 32 + lane] = S0;
    S4[((size_t)dst * NR + 1) * 32 + lane] = S1;
    S4[((size_t)dst * NR + 2) * 32 + lane] = S2;
    S4[((size_t)dst * NR + 3) * 32 + lane] = S3;
    S4[((size_t)dst * NR + 4) * 32 + lane] = S4r;
}

// ---------------- dense RM transform: aggr[n] = sum_r S[n,r] @ RM_r ----------
// 64 rows x 128 cols per block; RM_r staged per relation (amortized over 64 dsts).
__global__ __launch_bounds__(256) void k_rm_gemm(const float* __restrict__ RM) {
    __shared__ float As[NHID][68];
    __shared__ float Bs[32][128];
    int tid = threadIdx.x;
    int n0 = blockIdx.x * 64;
    int tm = tid >> 5, tn = tid & 31;
    int h = tn >> 3;   // cols tn*4..tn*4+3 all in head h

    float acc[8][4];
#pragma unroll
    for (int j = 0; j < 8; j++)
#pragma unroll
        for (int i = 0; i < 4; i++) acc[j][i] = 0.f;

    for (int r = 0; r < NR; r++) {
        // As[k][m] = S[n0+m, r, k]; m = s&63 -> conflict-free STS
#pragma unroll
        for (int it = 0; it < 8; it++) {
            int s = tid + it * 256;
            int m = s & 63, k4 = (s >> 6) * 4;
            int n = n0 + m; if (n >= NN) n = NN - 1;
            float4 sv = *(const float4*)(d_S + ((size_t)n * NR + r) * NHID + k4);
            As[k4 + 0][m] = sv.x; As[k4 + 1][m] = sv.y;
            As[k4 + 2][m] = sv.z; As[k4 + 3][m] = sv.w;
        }
        // Bs[i][h*32+d] = RM[r,h,i,d]  (32 rows x 128 cols = 1024 float4s)
#pragma unroll
        for (int it = 0; it < 4; it++) {
            int s = tid + it * 256;
            int i = s >> 5, c4 = (s & 31) * 4;
            int bh = c4 >> 5, d = c4 & 31;
            *(float4*)&Bs[i][c4] =
                *(const float4*)(RM + (((size_t)(r * NH + bh) * DK + i) * DK + d));
        }
        __syncthreads();
#pragma unroll
        for (int kk = 0; kk < DK; kk++) {
            float4 a0 = *(const float4*)&As[h * DK + kk][tm * 8];
            float4 a1 = *(const float4*)&As[h * DK + kk][tm * 8 + 4];
            float4 bv = *(const float4*)&Bs[kk][tn * 4];
            float av[8] = {a0.x, a0.y, a0.z, a0.w, a1.x, a1.y, a1.z, a1.w};
#pragma unroll
            for (int j = 0; j < 8; j++) {
                acc[j][0] += av[j] * bv.x;
                acc[j][1] += av[j] * bv.y;
                acc[j][2] += av[j] * bv.z;
                acc[j][3] += av[j] * bv.w;
            }
        }
        __syncthreads();
    }

#pragma unroll
    for (int j = 0; j < 8; j++) {
        int n = n0 + tm * 8 + j;
        if (n < NN) {
            float4 v;
            v.x = acc[j][0]; v.y = acc[j][1]; v.z = acc[j][2]; v.w = acc[j][3];
            *(float4*)(d_aggr + (size_t)n * NHID + tn * 4) = v;
        }
    }
}

// ---------------- launch ----------------
extern "C" void kernel_launch(void* const* d_in, const int* in_sizes, int n_in,
                              void* d_out, int out_size) {
    (void)in_sizes; (void)n_in; (void)out_size;
    const float* node_feature = (const float*)d_in[0];
    const float* adapt_W = (const float*)d_in[1];
    const float* adapt_b = (const float*)d_in[2];
    const float* Wk = (const float*)d_in[3];
    const float* bk = (const float*)d_in[4];
    const float* Wq = (const float*)d_in[5];
    const float* bq = (const float*)d_in[6];
    const float* Wv = (const float*)d_in[7];
    const float* bv = (const float*)d_in[8];
    const float* Wa = (const float*)d_in[9];
    const float* ba = (const float*)d_in[10];
    const float* rel_pri = (const float*)d_in[11];
    const float* rel_att = (const float*)d_in[12];
    const float* rel_msg = (const float*)d_in[13];
    const float* skip = (const float*)d_in[14];
    const float* rte_emb = (const float*)d_in[15];
    const float* rte_W = (const float*)d_in[16];
    const float* rte_b = (const float*)d_in[17];
    const int* node_type = (const int*)d_in[18];
    const int* edge_index = (const int*)d_in[19];
    const int* edge_type = (const int*)d_in[20];
    const int* edge_time = (const int*)d_in[21];
    float* out = (float*)d_out;

    void* p;
    float *p_h, *p_h2, *p_Kn, *p_Vn, *p_Qn, *p_QR, *p_aggr, *p_Krte, *p_Vrte;
    int *p_cnt, *p_indeg;
    cudaGetSymbolAddress(&p, d_h);     p_h = (float*)p;
    cudaGetSymbolAddress(&p, d_h2);    p_h2 = (float*)p;
    cudaGetSymbolAddress(&p, d_Kn);    p_Kn = (float*)p;
    cudaGetSymbolAddress(&p, d_Vn);    p_Vn = (float*)p;
    cudaGetSymbolAddress(&p, d_Qn);    p_Qn = (float*)p;
    cudaGetSymbolAddress(&p, d_QR);    p_QR = (float*)p;
    cudaGetSymbolAddress(&p, d_aggr);  p_aggr = (float*)p;
    cudaGetSymbolAddress(&p, d_Krte);  p_Krte = (float*)p;
    cudaGetSymbolAddress(&p, d_Vrte);  p_Vrte = (float*)p;
    cudaGetSymbolAddress(&p, d_cnt);   p_cnt = (int*)p;
    cudaGetSymbolAddress(&p, d_indeg); p_indeg = (int*)p;

    const int NBN = (NN + 255) / 256;
    const int NBE = (NE + 255) / 256;
    const int GT = NN / 64 + NT + 2;   // upper bound on typed-gemm tiles
    const float inv_sqrt_dk = 0.17677669529663687f; // 1/sqrt(32)

    // type bucketing
    cudaMemsetAsync(p_cnt, 0, NT * sizeof(int));
    k_count<<<NBN, 256>>>(node_type);
    k_scan<<<1, 1>>>();
    k_scatter<<<NBN, 256>>>(node_type);

    // CSR by dst (once)
    cudaMemsetAsync(p_indeg, 0, NN * sizeof(int));
    k_indeg<<<NBE, 256>>>(edge_index);
    k_csr_scan<<<1, 1024>>>();
    k_csr_scatter<<<NBE, 256>>>(edge_index, edge_type, edge_time, node_type);

    // input adaptation: h = gelu(x @ adapt_W[t] + adapt_b[t])
    typed_gemm<INDIM, 1, 0><<<GT, 256>>>(node_feature, adapt_W, adapt_b,
                                         nullptr, nullptr, p_h);

    const float* hin = p_h;
    for (int l = 0; l < NLAYERS; l++) {
        const float* Wk_l = Wk + (size_t)l * NT * NHID * NHID;
        const float* Wq_l = Wq + (size_t)l * NT * NHID * NHID;
        const float* Wv_l = Wv + (size_t)l * NT * NHID * NHID;
        const float* Wa_l = Wa + (size_t)l * NT * NHID * NHID;
        const float* bk_l = bk + (size_t)l * NT * NHID;
        const float* bq_l = bq + (size_t)l * NT * NHID;
        const float* bv_l = bv + (size_t)l * NT * NHID;
        const float* ba_l = ba + (size_t)l * NT * NHID;
        const float* ra_l = rel_att + (size_t)l * NR * NH * DK * DK;
        const float* rm_l = rel_msg + (size_t)l * NR * NH * DK * DK;
        const float* pri_l = rel_pri + (size_t)l * NR * NH;
        const float* skip_l = skip + (size_t)l * NT;
        float* hout = (l == NLAYERS - 1) ? out : p_h2;

        // per-node K/Q/V
        typed_gemm<NHID, 0, 0><<<GT, 256>>>(hin, Wk_l, bk_l, nullptr, nullptr, p_Kn);
        typed_gemm<NHID, 0, 0><<<GT, 256>>>(hin, Wq_l, bq_l, nullptr, nullptr, p_Qn);
        typed_gemm<NHID, 0, 0><<<GT, 256>>>(hin, Wv_l, bv_l, nullptr, nullptr, p_Vn);

        // RTE tables
        k_rtetab<<<MAXLEN, NHID>>>(rte_emb, rte_W + (size_t)l * NHID * NHID,
                                   rte_b + (size_t)l * NHID);
        {
            dim3 g(MAXLEN, NT);
            k_rteproj<<<g, NHID>>>(Wk_l, p_Krte);
            k_rteproj<<<g, NHID>>>(Wv_l, p_Vrte);
        }

        // relation-transformed Q per node (pri/sqrt(dk) folded in)
        qr_kernel<<<(NN + 63) / 64, 640>>>(p_Qn, ra_l, pri_l, inv_sqrt_dk, p_QR);

        // CSR gather (no smem, no atomics) then dense RM transform
        k_edge_gather<<<(NN * 32 + 511) / 512, 512>>>();
        k_rm_gemm<<<(NN + 63) / 64, 256>>>(rm_l);

        // output transform + gated skip, with normalize+GELU fused into A-load
        typed_gemm<NHID, 2, 1><<<GT, 256>>>(p_aggr, Wa_l, ba_l, skip_l, hin, hout);
        hin = hout;
        if (l == 0) { float* tmp = p_h; p_h = p_h2; p_h2 = tmp; }
    }
}